// round 5
// baseline (speedup 1.0000x reference)
#include <cuda_runtime.h>
#include <cstdint>

#define NN_MAX 50000
#define NE_MAX 800000
#define FH 64

// Scratch
__device__ float  g_deg[NN_MAX];
__device__ float4 g_er[NE_MAX];     // packed edge record: (row, col, norm, pad)
__device__ float  g_tx1[NN_MAX * FH];
__device__ float  g_p2[NN_MAX * FH];
__device__ float  g_Wc[192 * 136];  // combined weights, [k][n] stride 136, tf32-rounded

__device__ __forceinline__ void red_add_v4(float* a, float x, float y, float z, float w) {
    asm volatile("red.global.add.v4.f32 [%0], {%1,%2,%3,%4};"
                 :: "l"(a), "f"(x), "f"(y), "f"(z), "f"(w) : "memory");
}
__device__ __forceinline__ uint32_t f2tf32(float f) {
    uint32_t u;
    asm("cvt.rna.tf32.f32 %0, %1;" : "=r"(u) : "f"(f));
    return u;
}
__device__ __forceinline__ float fast_sigmoid(float x) { return 1.f / (1.f + __expf(-x)); }
__device__ __forceinline__ float fast_tanh(float x) {
    float t = __expf(-2.f * fabsf(x));
    float r = (1.f - t) / (1.f + t);
    return copysignf(r, x);
}

// ---------------------------------------------------------------------------
__global__ void k_zero(int n) {
    int t = blockIdx.x * blockDim.x + threadIdx.x;
    int nt = n * (FH / 4);
    float4 z = make_float4(0.f, 0.f, 0.f, 0.f);
    if (t < nt)              ((float4*)g_tx1)[t] = z;
    else if (t < 2 * nt)     ((float4*)g_p2)[t - nt] = z;
    else if (t < 2 * nt + n) g_deg[t - 2 * nt] = 0.f;
}

__global__ void k_deg(const int* __restrict__ row, const float* __restrict__ w, int ne) {
    int e = blockIdx.x * blockDim.x + threadIdx.x;
    if (e < ne) atomicAdd(g_deg + row[e], w[e]);
}

// Pack (row, col, norm) into one 16B record per edge
__global__ void k_pack(const int* __restrict__ row, const int* __restrict__ col,
                       const float* __restrict__ w, int ne) {
    int e = blockIdx.x * blockDim.x + threadIdx.x;
    if (e >= ne) return;
    int r = row[e], c = col[e];
    float dr = g_deg[r], dc = g_deg[c];
    float ir = dr > 0.f ? rsqrtf(dr) : 0.f;
    float ic = dc > 0.f ? rsqrtf(dc) : 0.f;
    float nm = -ir * w[e] * ic;
    g_er[e] = make_float4(__int_as_float(r), __int_as_float(c), nm, 0.f);
}

// Propagation: 4 threads/edge, each thread handles 4 float4 quads.
// pass 0: x -> tx1 ; pass 1: tx1 -> p2
__global__ void k_prop(const float* __restrict__ xsrc, int pass, int ne) {
    int t = blockIdx.x * blockDim.x + threadIdx.x;
    int e = t >> 2, q = t & 3;
    if (e >= ne) return;
    const float* src = pass ? g_tx1 : xsrc;
    float* dst = pass ? g_p2 : g_tx1;
    float4 rec = g_er[e];
    int r = __float_as_int(rec.x), c = __float_as_int(rec.y);
    float nm = rec.z;
    const float* sr = src + r * FH;
    float* dr = dst + c * FH;
    float4 v0 = *(const float4*)(sr + (q)      * 4);
    float4 v1 = *(const float4*)(sr + (q + 4)  * 4);
    float4 v2 = *(const float4*)(sr + (q + 8)  * 4);
    float4 v3 = *(const float4*)(sr + (q + 12) * 4);
    red_add_v4(dr + (q)      * 4, nm * v0.x, nm * v0.y, nm * v0.z, nm * v0.w);
    red_add_v4(dr + (q + 4)  * 4, nm * v1.x, nm * v1.y, nm * v1.z, nm * v1.w);
    red_add_v4(dr + (q + 8)  * 4, nm * v2.x, nm * v2.y, nm * v2.z, nm * v2.w);
    red_add_v4(dr + (q + 12) * 4, nm * v3.x, nm * v3.y, nm * v3.z, nm * v3.w);
}

// Combined weights B[k][n] (stride 136), tf32-rounded:
//   k<64: W0-W2 ; 64..127: W1 ; 128..191: 2*W2 ; n<64 -> Wxz else Wxh
__global__ void k_comb(const float* __restrict__ Wxz, const float* __restrict__ Wxh) {
    int t = blockIdx.x * blockDim.x + threadIdx.x;
    if (t >= 192 * 128) return;
    int k = t >> 7, j = t & 127;
    const float* W = (j < 64) ? Wxz : Wxh;
    int jj = j & 63;
    float v;
    if (k < 64)       v = W[k * 64 + jj] - W[2 * 4096 + k * 64 + jj];
    else if (k < 128) v = W[4096 + (k - 64) * 64 + jj];
    else              v = 2.f * W[2 * 4096 + (k - 128) * 64 + jj];
    g_Wc[k * 136 + j] = __uint_as_float(f2tf32(v));
}

// ---------------------------------------------------------------------------
// k_final: per block 128 nodes; D[128x128] = A[128x192] @ B[192x128] via
// mma.sync.m16n8k8.tf32, then gates + head.
#define A_STR 196
#define B_STR 136
#define Y_STR 132
#define SM_BZ   0
#define SM_BH   256
#define SM_WLIN 512
#define SM_A    1024
#define SM_B    (SM_A + 128 * A_STR * 4)
#define SMEM_BYTES (SM_B + 192 * B_STR * 4)

__device__ __forceinline__ void mma8(float* c, const uint32_t* a, const uint32_t* b) {
    asm volatile("mma.sync.aligned.m16n8k8.row.col.f32.tf32.tf32.f32 "
                 "{%0,%1,%2,%3}, {%4,%5,%6,%7}, {%8,%9}, {%0,%1,%2,%3};"
                 : "+f"(c[0]), "+f"(c[1]), "+f"(c[2]), "+f"(c[3])
                 : "r"(a[0]), "r"(a[1]), "r"(a[2]), "r"(a[3]), "r"(b[0]), "r"(b[1]));
}

__global__ void __launch_bounds__(256, 1)
k_final(const float* __restrict__ x,
        const float* __restrict__ bxz, const float* __restrict__ bhz,
        const float* __restrict__ bxh, const float* __restrict__ bhh,
        const float* __restrict__ Wlin, const float* __restrict__ blin,
        float* __restrict__ out, int n) {
    extern __shared__ __align__(16) char smem[];
    float* sBz = (float*)(smem + SM_BZ);
    float* sBh = (float*)(smem + SM_BH);
    float* sWl = (float*)(smem + SM_WLIN);
    float* As  = (float*)(smem + SM_A);
    float* Bs  = (float*)(smem + SM_B);
    const uint32_t* Au = (const uint32_t*)As;
    const uint32_t* Bu = (const uint32_t*)Bs;

    int tid = threadIdx.x, wid = tid >> 5, lane = tid & 31;
    int blk = blockIdx.x;

    for (int t = tid; t < 6528; t += 256)
        ((float4*)Bs)[t] = ((const float4*)g_Wc)[t];

    for (int idx = tid; idx < 128 * 48; idx += 256) {
        int m = idx / 48, seg = idx % 48;
        int g = blk * 128 + m;
        float4 v = make_float4(0.f, 0.f, 0.f, 0.f);
        if (g < n) {
            const float* src = (seg < 16) ? (x + g * FH + seg * 4)
                             : (seg < 32) ? (g_tx1 + g * FH + (seg - 16) * 4)
                                          : (g_p2 + g * FH + (seg - 32) * 4);
            v = *(const float4*)src;
        }
        float4 o;
        o.x = __uint_as_float(f2tf32(v.x));
        o.y = __uint_as_float(f2tf32(v.y));
        o.z = __uint_as_float(f2tf32(v.z));
        o.w = __uint_as_float(f2tf32(v.w));
        *(float4*)(As + m * A_STR + seg * 4) = o;
    }

    if (tid < 64) {
        sBz[tid] = bxz[tid] + bhz[tid];
        sBh[tid] = bxh[tid] + bhh[tid];
    }
    if (tid < 128) sWl[tid] = Wlin[tid];
    __syncthreads();

    int mw = wid >> 2, nw = wid & 3;
    int g8 = lane >> 2, t4 = lane & 3;
    int m0 = mw * 64, n0 = nw * 32;

    float acc[4][4][4];
    #pragma unroll
    for (int mt = 0; mt < 4; ++mt)
        #pragma unroll
        for (int nt = 0; nt < 4; ++nt)
            #pragma unroll
            for (int e = 0; e < 4; ++e) acc[mt][nt][e] = 0.f;

    #pragma unroll 4
    for (int ks = 0; ks < 24; ++ks) {
        int k0 = ks * 8;
        uint32_t a[4][4];
        #pragma unroll
        for (int mt = 0; mt < 4; ++mt) {
            int r0 = m0 + mt * 16;
            a[mt][0] = Au[(r0 + g8)     * A_STR + k0 + t4];
            a[mt][1] = Au[(r0 + g8 + 8) * A_STR + k0 + t4];
            a[mt][2] = Au[(r0 + g8)     * A_STR + k0 + t4 + 4];
            a[mt][3] = Au[(r0 + g8 + 8) * A_STR + k0 + t4 + 4];
        }
        uint32_t b[4][2];
        #pragma unroll
        for (int nt = 0; nt < 4; ++nt) {
            int c0 = n0 + nt * 8;
            b[nt][0] = Bu[(k0 + t4)     * B_STR + c0 + g8];
            b[nt][1] = Bu[(k0 + t4 + 4) * B_STR + c0 + g8];
        }
        #pragma unroll
        for (int mt = 0; mt < 4; ++mt)
            #pragma unroll
            for (int nt = 0; nt < 4; ++nt)
                mma8(acc[mt][nt], a[mt], b[nt]);
    }
    __syncthreads();

    float* Ys = As;
    #pragma unroll
    for (int mt = 0; mt < 4; ++mt) {
        #pragma unroll
        for (int nt = 0; nt < 4; ++nt) {
            int r = m0 + mt * 16 + g8;
            int c = n0 + nt * 8 + 2 * t4;
            Ys[r * Y_STR + c]           = acc[mt][nt][0];
            Ys[r * Y_STR + c + 1]       = acc[mt][nt][1];
            Ys[(r + 8) * Y_STR + c]     = acc[mt][nt][2];
            Ys[(r + 8) * Y_STR + c + 1] = acc[mt][nt][3];
        }
    }
    __syncthreads();

    for (int t = tid; t < 128 * 64; t += 256) {
        int i = t >> 6, j = t & 63;
        float cz = Ys[i * Y_STR + j]      + sBz[j];
        float ch = Ys[i * Y_STR + 64 + j] + sBh[j];
        float z  = fast_sigmoid(cz);
        float ht = fast_tanh(ch);
        Ys[i * Y_STR + j] = fast_tanh((1.f - z) * ht);
    }
    __syncthreads();

    {
        int i = tid >> 1, c = tid & 1;
        int g = blk * 128 + i;
        if (g < n) {
            float s = blin[c];
            #pragma unroll 8
            for (int jj = 0; jj < 64; ++jj)
                s = fmaf(Ys[i * Y_STR + jj], sWl[2 * jj + c], s);
            out[g * 2 + c] = fast_sigmoid(s);
        }
    }
}

// ---------------------------------------------------------------------------
extern "C" void kernel_launch(void* const* d_in, const int* in_sizes, int n_in,
                              void* d_out, int out_size) {
    const float* x    = (const float*)d_in[0];
    const int*   ei   = (const int*)d_in[1];
    const float* ew   = (const float*)d_in[2];
    const float* Wxz  = (const float*)d_in[3];
    const float* bxz  = (const float*)d_in[4];
    const float* bhz  = (const float*)d_in[6];
    const float* Wxh  = (const float*)d_in[11];
    const float* bxh  = (const float*)d_in[12];
    const float* bhh  = (const float*)d_in[14];
    const float* Wlin = (const float*)d_in[15];
    const float* blin = (const float*)d_in[16];
    float* out = (float*)d_out;

    int n  = in_sizes[0] / FH;
    int ne = in_sizes[2];
    const int* row = ei;
    const int* col = ei + ne;

    cudaFuncSetAttribute(k_final, cudaFuncAttributeMaxDynamicSharedMemorySize, SMEM_BYTES);

    int zthreads = 2 * n * (FH / 4) + n;
    k_zero<<<(zthreads + 255) / 256, 256>>>(n);
    k_deg<<<(ne + 255) / 256, 256>>>(row, ew, ne);
    k_pack<<<(ne + 255) / 256, 256>>>(row, col, ew, ne);
    k_prop<<<(ne * 4 + 255) / 256, 256>>>(x, 0, ne);
    k_prop<<<(ne * 4 + 255) / 256, 256>>>(x, 1, ne);
    k_comb<<<96, 256>>>(Wxz, Wxh);
    k_final<<<(n + 127) / 128, 256, SMEM_BYTES>>>(x, bxz, bhz, bxh, bhh, Wlin, blin, out, n);
}